// round 3
// baseline (speedup 1.0000x reference)
#include <cuda_runtime.h>

#define IN_F 8192
#define OUT_F 8192
#define THRESH_F 50.0f
#define ROWS_PER_BLOCK 8
#define THREADS 256
#define MV_BLOCKS (OUT_F / ROWS_PER_BLOCK)   // 1024
#define UPD_BLOCKS 64
#define UPD_THREADS 128

// Scratch between kernels (no allocations allowed). Fully overwritten every
// launch -> deterministic across graph replays.
__device__ float g_current[OUT_F];
__device__ __align__(16) float g_partial[MV_BLOCKS];   // per-block spike counts

// Kernel 1: binarized matvec + spike decision + per-block spike partial.
__global__ void __launch_bounds__(THREADS, 6) snn_matvec_kernel(
    const float* __restrict__ spike_input,   // [IN_F]
    const float* __restrict__ syn,           // [OUT_F, IN_F] row-major
    const float* __restrict__ v_mem,         // [OUT_F]
    const float* __restrict__ v_th,          // [OUT_F]
    const float* __restrict__ noise,         // [OUT_F]
    float* __restrict__ out)                 // out[0:OUT_F] = spikes
{
    __shared__ float4 s_spike[IN_F / 4];     // 32 KB
    __shared__ float  s_spk[ROWS_PER_BLOCK];

    const int tid = threadIdx.x;

    // Stage spike vector into shared (reused by all 8 rows in this block).
    const float4* sp4 = reinterpret_cast<const float4*>(spike_input);
    #pragma unroll
    for (int i = 0; i < (IN_F / 4) / THREADS; i++) {
        s_spike[tid + i * THREADS] = sp4[tid + i * THREADS];
    }
    __syncthreads();

    const int warp = tid >> 5;
    const int lane = tid & 31;
    const int row  = blockIdx.x * ROWS_PER_BLOCK + warp;

    const float4* r4 = reinterpret_cast<const float4*>(syn + (size_t)row * IN_F);

    float acc0 = 0.0f, acc1 = 0.0f;
    // 2048 float4 per row / 32 lanes = 64 float4 per lane; 2 per iteration.
    #pragma unroll 8
    for (int it = 0; it < (IN_F / 8) / 32; it++) {
        const int i0 = (it * 2 + 0) * 32 + lane;
        const int i1 = (it * 2 + 1) * 32 + lane;
        const float4 w0 = __ldcs(&r4[i0]);   // streaming: no reuse, evict-first
        const float4 w1 = __ldcs(&r4[i1]);
        const float4 s0 = s_spike[i0];
        const float4 s1 = s_spike[i1];
        if (w0.x > THRESH_F) acc0 += s0.x;
        if (w0.y > THRESH_F) acc1 += s0.y;
        if (w0.z > THRESH_F) acc0 += s0.z;
        if (w0.w > THRESH_F) acc1 += s0.w;
        if (w1.x > THRESH_F) acc0 += s1.x;
        if (w1.y > THRESH_F) acc1 += s1.y;
        if (w1.z > THRESH_F) acc0 += s1.z;
        if (w1.w > THRESH_F) acc1 += s1.w;
    }
    float acc = acc0 + acc1;

    // Warp reduce (exact: small integers).
    #pragma unroll
    for (int o = 16; o > 0; o >>= 1) {
        acc += __shfl_xor_sync(0xFFFFFFFFu, acc, o);
    }

    if (lane == 0) {
        g_current[row] = acc;
        const float pot = v_mem[row] + acc + noise[row];
        const float spk = (pot >= v_th[row]) ? 1.0f : 0.0f;
        out[row] = spk;
        s_spk[warp] = spk;
    }
    __syncthreads();

    if (tid == 0) {
        float p = 0.0f;
        #pragma unroll
        for (int w = 0; w < ROWS_PER_BLOCK; w++) p += s_spk[w];
        g_partial[blockIdx.x] = p;
    }
}

// Kernel 2: sum 1024 per-block partials (redundantly per block; exact integer
// sums) + elementwise state update. All independent loads issued up front so
// the two memory-latency chains overlap.
__global__ void __launch_bounds__(UPD_THREADS) snn_update_kernel(
    const float* __restrict__ v_mem,
    const float* __restrict__ v_th,
    float* __restrict__ out)   // [spikes | v_mem_new | v_th_new]
{
    __shared__ float red[UPD_THREADS / 32];

    const int tid = threadIdx.x;
    const int o   = blockIdx.x * UPD_THREADS + tid;

    // Independent loads first (overlap latencies).
    const float s   = out[o];
    const float cur = g_current[o];
    const float vm  = v_mem[o];
    const float vt0 = v_th[o];

    const float4* p4 = reinterpret_cast<const float4*>(g_partial);
    const float4 a = p4[tid];                       // 1024 partials = 256 float4
    const float4 b = p4[tid + UPD_THREADS];

    float local = ((a.x + a.y) + (a.z + a.w)) + ((b.x + b.y) + (b.z + b.w));
    #pragma unroll
    for (int off = 16; off > 0; off >>= 1) {
        local += __shfl_xor_sync(0xFFFFFFFFu, local, off);
    }
    if ((tid & 31) == 0) red[tid >> 5] = local;
    __syncthreads();

    float total = red[0];
    #pragma unroll
    for (int w = 1; w < UPD_THREADS / 32; w++) total += red[w];

    const float inhibition = total * 0.5f;

    const float v_new = (vm - inhibition + cur) * (1.0f - s) * 0.5f;

    float vt = vt0 + (s - 0.1f) * 0.01f;
    vt = fminf(fmaxf(vt, 0.2f), 5.0f);

    out[OUT_F + o]     = v_new;
    out[2 * OUT_F + o] = vt;
}

extern "C" void kernel_launch(void* const* d_in, const int* in_sizes, int n_in,
                              void* d_out, int out_size)
{
    const float* spike_input = (const float*)d_in[0];   // [1, 8192]
    const float* syn         = (const float*)d_in[1];   // [8192, 8192]
    const float* v_mem       = (const float*)d_in[2];   // [8192]
    const float* v_th        = (const float*)d_in[3];   // [8192]
    const float* noise       = (const float*)d_in[4];   // [8192]
    float* out = (float*)d_out;                          // 3 * 8192 floats

    snn_matvec_kernel<<<MV_BLOCKS, THREADS>>>(
        spike_input, syn, v_mem, v_th, noise, out);
    snn_update_kernel<<<UPD_BLOCKS, UPD_THREADS>>>(v_mem, v_th, out);
}

// round 4
// speedup vs baseline: 1.2329x; 1.2329x over previous
#include <cuda_runtime.h>

#define IN_F 8192
#define OUT_F 8192
#define THRESH_F 50.0f
#define ROWS_PER_BLOCK 8
#define THREADS 256
#define MV_BLOCKS (OUT_F / ROWS_PER_BLOCK)   // 1024
#define UPD_BLOCKS 256
#define UPD_THREADS 32

// Scratch between kernels (no allocations allowed). Fully overwritten every
// launch -> deterministic across graph replays.
__device__ float g_current[OUT_F];
__device__ __align__(16) float g_partial[MV_BLOCKS];   // per-block spike counts

// Kernel 1: binarized matvec + spike decision + per-block spike partial.
// R2-proven inner loop: no reg cap, no streaming hints.
__global__ void __launch_bounds__(THREADS) snn_matvec_kernel(
    const float* __restrict__ spike_input,   // [IN_F]
    const float* __restrict__ syn,           // [OUT_F, IN_F] row-major
    const float* __restrict__ v_mem,         // [OUT_F]
    const float* __restrict__ v_th,          // [OUT_F]
    const float* __restrict__ noise,         // [OUT_F]
    float* __restrict__ out)                 // out[0:OUT_F] = spikes
{
    __shared__ float4 s_spike[IN_F / 4];     // 32 KB
    __shared__ float  s_spk[ROWS_PER_BLOCK];

    const int tid = threadIdx.x;

    // Stage spike vector into shared (reused by all 8 rows in this block).
    const float4* sp4 = reinterpret_cast<const float4*>(spike_input);
    #pragma unroll
    for (int i = 0; i < (IN_F / 4) / THREADS; i++) {
        s_spike[tid + i * THREADS] = sp4[tid + i * THREADS];
    }
    __syncthreads();

    const int warp = tid >> 5;
    const int lane = tid & 31;
    const int row  = blockIdx.x * ROWS_PER_BLOCK + warp;

    const float4* r4 = reinterpret_cast<const float4*>(syn + (size_t)row * IN_F);

    float acc0 = 0.0f, acc1 = 0.0f;
    // 2048 float4 per row / 32 lanes = 64 float4 per lane; 2 per iteration.
    #pragma unroll 8
    for (int it = 0; it < (IN_F / 8) / 32; it++) {
        const int i0 = (it * 2 + 0) * 32 + lane;
        const int i1 = (it * 2 + 1) * 32 + lane;
        const float4 w0 = r4[i0];
        const float4 w1 = r4[i1];
        const float4 s0 = s_spike[i0];
        const float4 s1 = s_spike[i1];
        if (w0.x > THRESH_F) acc0 += s0.x;
        if (w0.y > THRESH_F) acc1 += s0.y;
        if (w0.z > THRESH_F) acc0 += s0.z;
        if (w0.w > THRESH_F) acc1 += s0.w;
        if (w1.x > THRESH_F) acc0 += s1.x;
        if (w1.y > THRESH_F) acc1 += s1.y;
        if (w1.z > THRESH_F) acc0 += s1.z;
        if (w1.w > THRESH_F) acc1 += s1.w;
    }
    float acc = acc0 + acc1;

    // Warp reduce (exact: small integers).
    #pragma unroll
    for (int o = 16; o > 0; o >>= 1) {
        acc += __shfl_xor_sync(0xFFFFFFFFu, acc, o);
    }

    if (lane == 0) {
        g_current[row] = acc;
        const float pot = v_mem[row] + acc + noise[row];
        const float spk = (pot >= v_th[row]) ? 1.0f : 0.0f;
        out[row] = spk;
        s_spk[warp] = spk;
    }
    __syncthreads();

    if (tid == 0) {
        float p = 0.0f;
        #pragma unroll
        for (int w = 0; w < ROWS_PER_BLOCK; w++) p += s_spk[w];
        g_partial[blockIdx.x] = p;
    }
}

// Kernel 2: 256 blocks x 32 threads (one warp each, no smem sync).
// Each block redundantly sums the 1024 L2-hot partials (exact integer sums)
// and updates its 32-row slice. All independent loads issued up front.
__global__ void __launch_bounds__(UPD_THREADS) snn_update_kernel(
    const float* __restrict__ v_mem,
    const float* __restrict__ v_th,
    float* __restrict__ out)   // [spikes | v_mem_new | v_th_new]
{
    const int tid = threadIdx.x;   // 0..31
    const int o   = blockIdx.x * UPD_THREADS + tid;

    // Independent per-row loads first (overlap latencies).
    const float s   = out[o];
    const float cur = g_current[o];
    const float vm  = v_mem[o];
    const float vt0 = v_th[o];

    // 1024 partials = 256 float4; 8 float4 per lane, coalesced.
    const float4* p4 = reinterpret_cast<const float4*>(g_partial);
    float local = 0.0f;
    #pragma unroll
    for (int i = 0; i < 8; i++) {
        const float4 a = p4[tid + i * 32];
        local += (a.x + a.y) + (a.z + a.w);
    }
    #pragma unroll
    for (int off = 16; off > 0; off >>= 1) {
        local += __shfl_xor_sync(0xFFFFFFFFu, local, off);
    }

    const float inhibition = local * 0.5f;

    const float v_new = (vm - inhibition + cur) * (1.0f - s) * 0.5f;

    float vt = vt0 + (s - 0.1f) * 0.01f;
    vt = fminf(fmaxf(vt, 0.2f), 5.0f);

    out[OUT_F + o]     = v_new;
    out[2 * OUT_F + o] = vt;
}

extern "C" void kernel_launch(void* const* d_in, const int* in_sizes, int n_in,
                              void* d_out, int out_size)
{
    const float* spike_input = (const float*)d_in[0];   // [1, 8192]
    const float* syn         = (const float*)d_in[1];   // [8192, 8192]
    const float* v_mem       = (const float*)d_in[2];   // [8192]
    const float* v_th        = (const float*)d_in[3];   // [8192]
    const float* noise       = (const float*)d_in[4];   // [8192]
    float* out = (float*)d_out;                          // 3 * 8192 floats

    snn_matvec_kernel<<<MV_BLOCKS, THREADS>>>(
        spike_input, syn, v_mem, v_th, noise, out);
    snn_update_kernel<<<UPD_BLOCKS, UPD_THREADS>>>(v_mem, v_th, out);
}